// round 14
// baseline (speedup 1.0000x reference)
#include <cuda_runtime.h>
#include <cstdint>
#include <cstddef>

#define NS   2048
#define CD   512
#define GMAX 128

#if defined(__CUDA_ARCH_FEAT_SM103_ALL) || defined(__CUDA_ARCH_FEAT_SM100_ALL) || defined(__CUDA_ARCH_FAMILY_SPECIFIC__)
#define HAS_TCGEN05 1
#else
#define HAS_TCGEN05 0
#endif

// ---------------- device scratch ----------------
__device__ float g_Wn1[512 * 1024];    // conv1 weight as [N=co][K=kk*512+ci]
__device__ float g_Wn2[512 * 2048];    // conv2 weight as [N=co][K]
__device__ float g_Wat[4 * 512 * 512]; // wq^T, wk^T, wv^T, wo^T as [N][K]
__device__ float g_tmp1[NS * 16 * CD];
__device__ float g_tmp2[NS * 8 * CD];
__device__ float g_pooled[NS * CD];
__device__ float g_q[NS * CD];
__device__ float g_k[NS * CD];
__device__ float g_v[NS * CD];
__device__ float g_attnout[NS * CD];
__device__ float g_mw2[64];
__device__ int   g_counts[64];
__device__ int   g_offsets[64];
__device__ int   g_order[NS];

// ---------------- common helpers ----------------
__device__ __forceinline__ uint32_t to_tf32_u(float x) {
    uint32_t u;
    asm("cvt.rna.tf32.f32 %0, %1;" : "=r"(u) : "f"(x));
    return u;
}
__device__ __forceinline__ void mma_tf32(float* d, const uint32_t* a, const uint32_t* b) {
    asm volatile(
        "mma.sync.aligned.m16n8k8.row.col.f32.tf32.tf32.f32 "
        "{%0,%1,%2,%3}, {%4,%5,%6,%7}, {%8,%9}, {%0,%1,%2,%3};\n"
        : "+f"(d[0]), "+f"(d[1]), "+f"(d[2]), "+f"(d[3])
        : "r"(a[0]), "r"(a[1]), "r"(a[2]), "r"(a[3]), "r"(b[0]), "r"(b[1]));
}
__device__ __forceinline__ void cp_async16(uint32_t dst, const void* src) {
    asm volatile("cp.async.cg.shared.global [%0], [%1], 16;\n" :: "r"(dst), "l"(src));
}
__device__ __forceinline__ void cp_commit() {
    asm volatile("cp.async.commit_group;\n");
}
template <int N>
__device__ __forceinline__ void cp_wait() {
    asm volatile("cp.async.wait_group %0;\n" :: "n"(N));
}
__device__ __forceinline__ uint32_t elect_one_pred() {
    uint32_t pred;
    asm volatile(
        "{\n\t.reg .pred p;\n\telect.sync _|p, 0xFFFFFFFF;\n\t"
        "selp.b32 %0, 1, 0, p;\n\t}" : "=r"(pred));
    return pred;
}
__device__ __forceinline__ uint32_t swz128(uint32_t off) {
    return off ^ ((off >> 3) & 0x70u);
}

#define MBARRIER_INIT(mbar_smem_addr, count) \
    asm volatile("mbarrier.init.shared.b64 [%0], %1;" \
        :: "r"((uint32_t)(mbar_smem_addr)), "r"((uint32_t)(count)) : "memory")
#define MBARRIER_WAIT_PARITY(mbar_smem_addr, phase_parity) do { \
    uint32_t _mbar = (uint32_t)(mbar_smem_addr); \
    uint32_t _parity = (uint32_t)(phase_parity); \
    uint32_t _done; \
    asm volatile( \
        "{\n\t.reg .pred p;\n\t" \
        "mbarrier.try_wait.parity.acquire.cta.shared::cta.b64 p, [%1], %2;\n\t" \
        "selp.b32 %0, 1, 0, p;\n\t}" \
        : "=r"(_done) : "r"(_mbar), "r"(_parity) : "memory"); \
    if (!_done) { \
        asm volatile( \
            "{\n\t.reg .pred P1;\n\t" \
            "WAIT_LOOP_%=:\n\t" \
            "mbarrier.try_wait.parity.acquire.cta.shared::cta.b64 P1, [%0], %1, 0x989680;\n\t" \
            "@P1 bra.uni WAIT_DONE_%=;\n\t" \
            "bra.uni WAIT_LOOP_%=;\n\t" \
            "WAIT_DONE_%=:\n\t}" \
            :: "r"(_mbar), "r"(_parity) : "memory"); \
    } \
} while(0)

#if HAS_TCGEN05
// ---------------- tcgen05 plumbing (arch-specific targets only) ----------------
#define TCGEN05_ALLOC(smem_addr, nCols) \
    asm volatile("tcgen05.alloc.cta_group::1.sync.aligned.shared::cta.b32 [%0], %1;" \
        :: "r"((uint32_t)(smem_addr)), "r"((uint32_t)(nCols)) : "memory")
#define TCGEN05_DEALLOC(tmem_addr, nCols) \
    asm volatile("tcgen05.dealloc.cta_group::1.sync.aligned.b32 %0, %1;" \
        :: "r"(tmem_addr), "r"((uint32_t)(nCols)))
#define TCGEN05_COMMIT(mbar_smem_addr) \
    asm volatile("tcgen05.commit.cta_group::1.mbarrier::arrive::one.shared::cluster.b64 [%0];" \
        :: "r"((uint32_t)(mbar_smem_addr)) : "memory")
#define TCGEN05_FENCE_AFTER() \
    asm volatile("tcgen05.fence::after_thread_sync;" ::: "memory")
#define TCGEN05_FENCE_BEFORE() \
    asm volatile("tcgen05.fence::before_thread_sync;" ::: "memory")
#define TCGEN05_WAIT_LD() \
    asm volatile("tcgen05.wait::ld.sync.aligned;" ::: "memory")
#define TCGEN05_LD_32X32B_X32(r, tmem_addr) \
    asm volatile( \
        "tcgen05.ld.sync.aligned.32x32b.x32.b32 " \
        "{%0, %1, %2, %3, %4, %5, %6, %7, " \
        " %8, %9, %10, %11, %12, %13, %14, %15, " \
        " %16, %17, %18, %19, %20, %21, %22, %23, " \
        " %24, %25, %26, %27, %28, %29, %30, %31}, [%32];" \
        : "=r"((r)[0]),  "=r"((r)[1]),  "=r"((r)[2]),  "=r"((r)[3]), \
          "=r"((r)[4]),  "=r"((r)[5]),  "=r"((r)[6]),  "=r"((r)[7]), \
          "=r"((r)[8]),  "=r"((r)[9]),  "=r"((r)[10]), "=r"((r)[11]), \
          "=r"((r)[12]), "=r"((r)[13]), "=r"((r)[14]), "=r"((r)[15]), \
          "=r"((r)[16]), "=r"((r)[17]), "=r"((r)[18]), "=r"((r)[19]), \
          "=r"((r)[20]), "=r"((r)[21]), "=r"((r)[22]), "=r"((r)[23]), \
          "=r"((r)[24]), "=r"((r)[25]), "=r"((r)[26]), "=r"((r)[27]), \
          "=r"((r)[28]), "=r"((r)[29]), "=r"((r)[30]), "=r"((r)[31]) \
        : "r"(tmem_addr))

static constexpr uint64_t SMEM_DESC_BASE_SW128 =
    (uint64_t(2)  << 61) | (uint64_t(1) << 46) | (uint64_t(64) << 32) | (uint64_t(1) << 16);
__device__ __forceinline__ uint64_t make_desc(uint32_t base_addr) {
    return SMEM_DESC_BASE_SW128 | ((uint64_t)(base_addr >> 4) & 0x3FFF);
}
#define IDESC_TF32_128 0x8200910u

__device__ __forceinline__ void mma_tc_tf32(uint32_t d, uint64_t ad, uint64_t bd,
                                            uint32_t idesc, bool acc) {
    uint32_t en = acc ? 1u : 0u;
    uint32_t z = 0u;
    asm volatile(
        "{\n\t.reg .pred p;\n\t"
        "setp.ne.u32 p, %5, 0;\n\t"
        "tcgen05.mma.cta_group::1.kind::tf32 [%0], %1, %2, %3, {%4,%4,%4,%4}, p;\n\t"
        "}"
        :: "r"(d), "l"(ad), "l"(bd), "r"(idesc), "r"(z), "r"(en) : "memory");
}
#endif  // HAS_TCGEN05

// ---------------- cg1 tcgen05 GEMM body (M=128, N=512, 2-stage) ----------------
#define TCS_CTRL  1024
#define TCS_STAGE (80 * 1024)
#define TC_SMEM   (TCS_CTRL + 2 * TCS_STAGE)

__device__ __forceinline__ void gemm_tc_body(
    const float* __restrict__ A, const float* __restrict__ B,
    const float* __restrict__ bias, const float* __restrict__ res,
    float* __restrict__ C,
    const float* __restrict__ wp, const float* __restrict__ bp, float* __restrict__ out,
    int K, int m0, float* smem)
{
#if HAS_TCGEN05
    uint32_t sb;
    { uint64_t t = __cvta_generic_to_shared(smem); sb = (uint32_t)t; }
    const int tid = threadIdx.x;
    const int lane = tid & 31, wid = tid >> 5;

    if (wid == 0) TCGEN05_ALLOC(sb + 0, 512);
    if (tid == 0) { MBARRIER_INIT(sb + 8, 1); MBARRIER_INIT(sb + 16, 1); }
    __syncthreads();
    uint32_t tmem;
    asm volatile("ld.shared.b32 %0, [%1];" : "=r"(tmem) : "r"(sb + 0));

    const int NSLAB = K >> 5;

    auto issue = [&](int s) {
        const uint32_t base = sb + TCS_CTRL + (uint32_t)(s & 1) * TCS_STAGE;
        const int kt = s << 5;
#pragma unroll
        for (int p = 0; p < 4; p++) {
            const int id = tid + (p << 8);
            const int r = id >> 3;
            const uint32_t c = (uint32_t)(id & 7) << 4;
            cp_async16(base + swz128(r * 128u + c),
                       A + (size_t)(m0 + r) * K + kt + (c >> 2));
        }
        const uint32_t bbase = base + 16384u;
#pragma unroll
        for (int p = 0; p < 16; p++) {
            const int id = tid + (p << 8);
            const int rn = id >> 3;
            const uint32_t c = (uint32_t)(id & 7) << 4;
            cp_async16(bbase + ((uint32_t)(rn >> 7) << 14) + swz128((uint32_t)(rn & 127) * 128u + c),
                       B + (size_t)rn * K + kt + (c >> 2));
        }
        cp_commit();
    };

    int ph[2] = {0, 0};
    issue(0);
    for (int s = 0; s < NSLAB; s++) {
        if (s + 1 < NSLAB) {
            if (s + 1 >= 2) {
                const int st2 = (s + 1) & 1;
                MBARRIER_WAIT_PARITY(sb + 8 + st2 * 8, ph[st2]);
                ph[st2] ^= 1;
            }
            issue(s + 1);
        }
        if (s + 1 < NSLAB) cp_wait<1>(); else cp_wait<0>();
        asm volatile("fence.proxy.async;" ::: "memory");
        __syncthreads();
        if (wid == 0 && elect_one_pred()) {
            const int st = s & 1;
            const uint32_t abase = sb + TCS_CTRL + (uint32_t)st * TCS_STAGE;
            const uint64_t adesc = make_desc(abase);
#pragma unroll
            for (int k = 0; k < 4; k++) {
#pragma unroll
                for (int c = 0; c < 4; c++) {
                    const uint64_t bdesc = make_desc(abase + 16384u + (uint32_t)c * 16384u) + k * 2;
                    mma_tc_tf32(tmem + c * 128, adesc + k * 2, bdesc,
                                IDESC_TF32_128, !(s == 0 && k == 0));
                }
            }
            TCGEN05_COMMIT(sb + 8 + st * 8);
        }
    }

    {
        const int st = (NSLAB - 1) & 1;
        MBARRIER_WAIT_PARITY(sb + 8 + st * 8, ph[st]);
    }
    TCGEN05_FENCE_AFTER();

    if (tid < 256) { smem[256 + tid] = bias[tid]; smem[256 + 256 + tid] = bias[256 + tid]; }
    if (wp && tid < 256) { smem[768 + tid] = wp[tid]; smem[768 + 256 + tid] = wp[256 + tid]; }
    __syncthreads();
    const float* bias_s = smem + 256;
    const float* wp_s   = smem + 768;

    {
        const int sub = wid & 3;
        const int half = wid >> 2;
        const int row = m0 + sub * 32 + lane;
        float* crow = C ? (C + (size_t)row * 512) : nullptr;
        const float* rrow = res ? (res + (size_t)row * 512) : nullptr;
        float partial = 0.f;
#pragma unroll
        for (int ch = 0; ch < 8; ch++) {
            const int col0 = half * 256 + ch * 32;
            uint32_t r[32];
            TCGEN05_LD_32X32B_X32(r, tmem + col0);
            TCGEN05_WAIT_LD();
#pragma unroll
            for (int j = 0; j < 32; j += 4) {
                float4 v;
                v.x = __uint_as_float(r[j])     + bias_s[col0 + j];
                v.y = __uint_as_float(r[j + 1]) + bias_s[col0 + j + 1];
                v.z = __uint_as_float(r[j + 2]) + bias_s[col0 + j + 2];
                v.w = __uint_as_float(r[j + 3]) + bias_s[col0 + j + 3];
                if (rrow) {
                    const float4 rv = *(const float4*)(rrow + col0 + j);
                    v.x += rv.x; v.y += rv.y; v.z += rv.z; v.w += rv.w;
                }
                if (crow) *(float4*)(crow + col0 + j) = v;
                if (wp) {
                    partial += v.x * wp_s[col0 + j]     + v.y * wp_s[col0 + j + 1]
                             + v.z * wp_s[col0 + j + 2] + v.w * wp_s[col0 + j + 3];
                }
            }
        }
        if (wp) {
            smem[1280 + wid * 32 + lane] = partial;
            __syncthreads();
            if (wid < 4)
                out[m0 + wid * 32 + lane] =
                    smem[1280 + wid * 32 + lane] + smem[1280 + (wid + 4) * 32 + lane] + bp[0];
        }
    }
    TCGEN05_FENCE_BEFORE();
    __syncthreads();
    if (wid == 0) TCGEN05_DEALLOC(tmem, 512);
#else
    // --------- fallback (generic PTX pass): mma.sync, both operands K-major ---------
    const int tid = threadIdx.x;
    const int lane = tid & 31, wid = tid >> 5;
    const int wm = wid >> 2, wn = wid & 3;
    float* As = smem;
    float* Bs = smem + 128 * 36;
    float* opart = smem + 2 * 128 * 36;

    if (wp) { for (int i = tid; i < 128; i += 256) opart[i] = 0.f; }
    __syncthreads();

    float pd[4][2];
#pragma unroll
    for (int i = 0; i < 4; i++) { pd[i][0] = 0.f; pd[i][1] = 0.f; }

    for (int nc = 0; nc < 4; nc++) {
        float acc[4][4][4];
#pragma unroll
        for (int i = 0; i < 4; i++)
#pragma unroll
            for (int j = 0; j < 4; j++)
#pragma unroll
                for (int r = 0; r < 4; r++) acc[i][j][r] = 0.f;
        for (int kt = 0; kt < K; kt += 32) {
            __syncthreads();
#pragma unroll
            for (int p = 0; p < 4; p++) {
                const int id = tid + (p << 8);
                const int r = id >> 3, c = (id & 7) << 2;
                const float4 va = *(const float4*)(A + (size_t)(m0 + r) * K + kt + c);
                float4 t;
                t.x = __uint_as_float(to_tf32_u(va.x)); t.y = __uint_as_float(to_tf32_u(va.y));
                t.z = __uint_as_float(to_tf32_u(va.z)); t.w = __uint_as_float(to_tf32_u(va.w));
                *(float4*)(As + r * 36 + c) = t;
                const float4 vb = *(const float4*)(B + (size_t)(nc * 128 + r) * K + kt + c);
                float4 u;
                u.x = __uint_as_float(to_tf32_u(vb.x)); u.y = __uint_as_float(to_tf32_u(vb.y));
                u.z = __uint_as_float(to_tf32_u(vb.z)); u.w = __uint_as_float(to_tf32_u(vb.w));
                *(float4*)(Bs + r * 36 + c) = u;
            }
            __syncthreads();
#pragma unroll
            for (int k8 = 0; k8 < 4; k8++) {
                uint32_t af[4][4], bf[4][2];
#pragma unroll
                for (int mf = 0; mf < 4; mf++) {
                    const int r = wm * 64 + mf * 16 + (lane >> 2);
                    const int c = k8 * 8 + (lane & 3);
                    af[mf][0] = __float_as_uint(As[r * 36 + c]);
                    af[mf][1] = __float_as_uint(As[(r + 8) * 36 + c]);
                    af[mf][2] = __float_as_uint(As[r * 36 + c + 4]);
                    af[mf][3] = __float_as_uint(As[(r + 8) * 36 + c + 4]);
                }
#pragma unroll
                for (int nf = 0; nf < 4; nf++) {
                    const int cb = wn * 32 + nf * 8 + (lane >> 2);
                    const int rb = k8 * 8 + (lane & 3);
                    bf[nf][0] = __float_as_uint(Bs[cb * 36 + rb]);
                    bf[nf][1] = __float_as_uint(Bs[cb * 36 + rb + 4]);
                }
#pragma unroll
                for (int mf = 0; mf < 4; mf++)
#pragma unroll
                    for (int nf = 0; nf < 4; nf++) mma_tf32(acc[mf][nf], af[mf], bf[nf]);
            }
        }
#pragma unroll
        for (int mf = 0; mf < 4; mf++) {
            const int r0 = m0 + wm * 64 + mf * 16 + (lane >> 2);
#pragma unroll
            for (int nf = 0; nf < 4; nf++) {
                const int c0 = nc * 128 + wn * 32 + nf * 8 + ((lane & 3) << 1);
                float v0 = acc[mf][nf][0] + bias[c0];
                float v1 = acc[mf][nf][1] + bias[c0 + 1];
                float v2 = acc[mf][nf][2] + bias[c0];
                float v3 = acc[mf][nf][3] + bias[c0 + 1];
                if (res) {
                    v0 += res[(size_t)r0 * 512 + c0];
                    v1 += res[(size_t)r0 * 512 + c0 + 1];
                    v2 += res[(size_t)(r0 + 8) * 512 + c0];
                    v3 += res[(size_t)(r0 + 8) * 512 + c0 + 1];
                }
                if (C) {
                    C[(size_t)r0 * 512 + c0]           = v0;
                    C[(size_t)r0 * 512 + c0 + 1]       = v1;
                    C[(size_t)(r0 + 8) * 512 + c0]     = v2;
                    C[(size_t)(r0 + 8) * 512 + c0 + 1] = v3;
                }
                if (wp) {
                    pd[mf][0] += v0 * wp[c0] + v1 * wp[c0 + 1];
                    pd[mf][1] += v2 * wp[c0] + v3 * wp[c0 + 1];
                }
            }
        }
    }
    if (wp) {
#pragma unroll
        for (int mf = 0; mf < 4; mf++) {
            const int r0 = wm * 64 + mf * 16 + (lane >> 2);
            atomicAdd(&opart[r0], pd[mf][0]);
            atomicAdd(&opart[r0 + 8], pd[mf][1]);
        }
        __syncthreads();
        for (int i = tid; i < 128; i += 256) out[m0 + i] = opart[i] + bp[0];
    }
#endif
}

// ---------------- conv GEMM: M=256 x N=256 tiles, 3-stage, lowest L2 traffic ----------------
#define CV_STAGE 65536
#define CV_SMEM  (1024 + 3 * CV_STAGE)   // 197632

__global__ void __launch_bounds__(256) gemm_tc_conv_kernel(
    const float* __restrict__ x,
    const float* __restrict__ conv1_b, const float* __restrict__ conv2_b,
    float* __restrict__ T1, float* __restrict__ T2)
{
    extern __shared__ float smem[];
    int K, m0, n0;
    const float* B; const float* bias_g; float* C;
    if (blockIdx.x < 128) {          // conv2: 64 supertiles x 2 N-halves
        K = 2048; C = T2; bias_g = conv2_b; B = g_Wn2;
        m0 = (blockIdx.x >> 1) << 8;
        n0 = (blockIdx.x & 1) << 8;
    } else {                          // conv1: 128 supertiles x 2 N-halves
        const int bi = blockIdx.x - 128;
        K = 1024; C = T1; bias_g = conv1_b; B = g_Wn1;
        m0 = (bi >> 1) << 8;
        n0 = (bi & 1) << 8;
    }
#if HAS_TCGEN05
    uint32_t sb;
    { uint64_t t = __cvta_generic_to_shared(smem); sb = (uint32_t)t; }
    const int tid = threadIdx.x;
    const int lane = tid & 31, wid = tid >> 5;

    if (wid == 0) TCGEN05_ALLOC(sb + 0, 512);
    if (tid == 0) {
#pragma unroll
        for (int st = 0; st < 3; st++) MBARRIER_INIT(sb + 8 + st * 8, 1);
    }
    __syncthreads();
    uint32_t tmem;
    asm volatile("ld.shared.b32 %0, [%1];" : "=r"(tmem) : "r"(sb + 0));

    const int NSLAB = K >> 5;

    auto issue = [&](int s) {
        const uint32_t base = sb + 1024u + (uint32_t)(s % 3) * CV_STAGE;
        const int kt = s << 5;
#pragma unroll
        for (int p = 0; p < 8; p++) {
            const int id = tid + (p << 8);
            const int r = id >> 3;
            const uint32_t c = (uint32_t)(id & 7) << 4;
            cp_async16(base + ((uint32_t)(r >> 7) << 14) + swz128((uint32_t)(r & 127) * 128u + c),
                       x + (size_t)(m0 + r) * K + kt + (c >> 2));
        }
        const uint32_t bbase = base + 32768u;
#pragma unroll
        for (int p = 0; p < 8; p++) {
            const int id = tid + (p << 8);
            const int rn = id >> 3;
            const uint32_t c = (uint32_t)(id & 7) << 4;
            cp_async16(bbase + ((uint32_t)(rn >> 7) << 14) + swz128((uint32_t)(rn & 127) * 128u + c),
                       B + (size_t)(n0 + rn) * K + kt + (c >> 2));
        }
        cp_commit();
    };

    int eph[3] = {0, 0, 0};
    issue(0); if (NSLAB > 1) issue(1);
    for (int s = 0; s < NSLAB; s++) {
        if (s + 2 < NSLAB) {
            const int st2 = (s + 2) % 3;
            if (s + 2 >= 3) {
                MBARRIER_WAIT_PARITY(sb + 8 + st2 * 8, eph[st2]);
                eph[st2] ^= 1;
            }
            issue(s + 2);
        }
        if (s + 2 < NSLAB) cp_wait<2>();
        else if (s + 1 < NSLAB) cp_wait<1>();
        else cp_wait<0>();
        asm volatile("fence.proxy.async;" ::: "memory");
        __syncthreads();
        if (wid == 0 && elect_one_pred()) {
            const int st = s % 3;
            const uint32_t base = sb + 1024u + (uint32_t)st * CV_STAGE;
#pragma unroll
            for (int k = 0; k < 4; k++) {
#pragma unroll
                for (int t = 0; t < 2; t++) {
                    const uint64_t adesc = make_desc(base + (uint32_t)t * 16384u) + k * 2;
#pragma unroll
                    for (int c = 0; c < 2; c++) {
                        const uint64_t bdesc = make_desc(base + 32768u + (uint32_t)c * 16384u) + k * 2;
                        mma_tc_tf32(tmem + t * 256 + c * 128, adesc, bdesc,
                                    IDESC_TF32_128, !(s == 0 && k == 0));
                    }
                }
            }
            TCGEN05_COMMIT(sb + 8 + st * 8);
        }
    }

    {
        const int st = (NSLAB - 1) % 3;
        MBARRIER_WAIT_PARITY(sb + 8 + st * 8, eph[st]);
    }
    TCGEN05_FENCE_AFTER();

    if (tid < 256) smem[256 + tid] = bias_g[n0 + tid];
    __syncthreads();
    const float* bias_s = smem + 256;

    {
        const int tile = wid >> 2;
        const int sub = wid & 3;
        const int row = m0 + tile * 128 + sub * 32 + lane;
        float* crow = C + (size_t)row * 512 + n0;
#pragma unroll
        for (int ch = 0; ch < 8; ch++) {
            const int col0 = ch * 32;
            uint32_t r[32];
            TCGEN05_LD_32X32B_X32(r, tmem + tile * 256 + col0);
            TCGEN05_WAIT_LD();
#pragma unroll
            for (int j = 0; j < 32; j += 4) {
                float4 v;
                v.x = __uint_as_float(r[j])     + bias_s[col0 + j];
                v.y = __uint_as_float(r[j + 1]) + bias_s[col0 + j + 1];
                v.z = __uint_as_float(r[j + 2]) + bias_s[col0 + j + 2];
                v.w = __uint_as_float(r[j + 3]) + bias_s[col0 + j + 3];
                *(float4*)(crow + col0 + j) = v;
            }
        }
    }
    TCGEN05_FENCE_BEFORE();
    __syncthreads();
    if (wid == 0) TCGEN05_DEALLOC(tmem, 512);
#else
    gemm_tc_body(x, B, bias_g, nullptr, C, nullptr, nullptr, nullptr, K, m0, smem);
    __syncthreads();
    gemm_tc_body(x, B, bias_g, nullptr, C, nullptr, nullptr, nullptr, K, m0 + 128, smem);
#endif
}

// fused QKV
__global__ void __launch_bounds__(256) gemm_tc_qkv_kernel(
    const float* __restrict__ A,
    const float* __restrict__ bq, const float* __restrict__ bk, const float* __restrict__ bv,
    float* __restrict__ Cq, float* __restrict__ Ck, float* __restrict__ Cv)
{
    extern __shared__ float smem[];
    const int z = blockIdx.y;
    const float* B    = g_Wat + ((size_t)z << 18);
    const float* bias = (z == 0) ? bq : (z == 1) ? bk : bv;
    float* C          = (z == 0) ? Cq : (z == 1) ? Ck : Cv;
    gemm_tc_body(A, B, bias, nullptr, C, nullptr, nullptr, nullptr, 512, blockIdx.x * 128, smem);
}

// out-proj + residual + fused final dot -> out
__global__ void __launch_bounds__(256) gemm_tc_out_kernel(
    const float* __restrict__ A, const float* __restrict__ bo,
    const float* __restrict__ res,
    const float* __restrict__ wp, const float* __restrict__ bp, float* __restrict__ out)
{
    extern __shared__ float smem[];
    const float* B = g_Wat + ((size_t)3 << 18);
    gemm_tc_body(A, B, bo, res, nullptr, wp, bp, out, 512, blockIdx.x * 128, smem);
}

// ---------------- merged weight prep (single launch) ----------------
__global__ void __launch_bounds__(256) prep_all_kernel(
    const float* __restrict__ c1w, const float* __restrict__ c2w,
    const float* __restrict__ wq, const float* __restrict__ wk,
    const float* __restrict__ wv, const float* __restrict__ wo,
    const float* __restrict__ w2, const float* __restrict__ b2)
{
    const int b = blockIdx.x;
    const int tid = threadIdx.x;
    if (b < 2048) {
        const int idx = b * 256 + tid;
        const int co = idx >> 10, k = idx & 1023;
        const int kk = k >> 9, ci = k & 511;
        g_Wn1[idx] = c1w[(size_t)co * 1024 + ci * 2 + kk];
    } else if (b < 6144) {
        const int idx = (b - 2048) * 256 + tid;
        const int co = idx >> 11, k = idx & 2047;
        const int kk = k >> 9, ci = k & 511;
        g_Wn2[idx] = c2w[(size_t)co * 2048 + ci * 4 + kk];
    } else if (b < 7168) {
        __shared__ float tile[32][33];
        const int wb = b - 6144;
        const int which = wb >> 8;
        const float* src = (which == 0) ? wq : (which == 1) ? wk : (which == 2) ? wv : wo;
        const int bx = wb & 15, by = (wb >> 4) & 15;
        const int tx = tid & 31, ty = tid >> 5;
#pragma unroll
        for (int i = 0; i < 32; i += 8)
            tile[ty + i][tx] = src[(by * 32 + ty + i) * 512 + bx * 32 + tx];
        __syncthreads();
        float* dst = g_Wat + ((size_t)which << 18);
#pragma unroll
        for (int i = 0; i < 32; i += 8)
            dst[(bx * 32 + ty + i) * 512 + by * 32 + tx] = tile[tx][ty + i];
    } else {
        if (tid < 56) {
            float s = 0.f;
            for (int ss = tid; ss < 56; ss++) s += w2[ss * 56 + tid];
            g_mw2[tid] = s * (1.f / 56.f);
        } else if (tid == 56) {
            float s = 0.f;
            for (int i = 0; i < 56; i++) s += b2[i];
            g_mw2[56] = s * (1.f / 56.f);
        }
    }
}

// ---------------- parallel deterministic industry grouping ----------------
__global__ void __launch_bounds__(1024) group_kernel(const int* __restrict__ ids) {
    __shared__ int sid[NS];
    __shared__ int scnt[64], soff[64];
    const int tid = threadIdx.x;
    const int warp = tid >> 5, lane = tid & 31;
    sid[tid] = ids[tid];
    sid[tid + 1024] = ids[tid + 1024];
    __syncthreads();
#pragma unroll
    for (int g = warp; g < 64; g += 32) {
        int cnt = 0;
        for (int c = 0; c < NS; c += 32)
            cnt += __popc(__ballot_sync(0xffffffffu, sid[c + lane] == g));
        if (lane == 0) scnt[g] = cnt;
    }
    __syncthreads();
    if (tid == 0) {
        int off = 0;
        for (int g = 0; g < 64; g++) {
            soff[g] = off; g_offsets[g] = off; g_counts[g] = scnt[g];
            off += scnt[g];
        }
    }
    __syncthreads();
#pragma unroll
    for (int g = warp; g < 64; g += 32) {
        int w = soff[g];
        for (int c = 0; c < NS; c += 32) {
            const bool hit = (sid[c + lane] == g);
            const unsigned m = __ballot_sync(0xffffffffu, hit);
            if (hit) g_order[w + __popc(m & ((1u << lane) - 1u))] = c + lane;
            w += __popc(m);
        }
    }
}

// ---------------- fused LN-stats + TriU1 + hardswish + folded(TriU2+mean) ----------------
// smem: T1s 8192 | T2s 4096 | W1s 3136 | b1s 64 | mw2s 64 | red 68 -> 15620 floats (~61KB)
// x is read directly from global in the v-build (coalesced) -> 3 CTAs/SM.
#define TRIU_SMEM (15680 * 4)

__global__ void __launch_bounds__(512) triu_pool_kernel(
    const float* __restrict__ x,
    const float* __restrict__ ln1g, const float* __restrict__ ln1b,
    const float* __restrict__ ln2g, const float* __restrict__ ln2b,
    const float* __restrict__ w1, const float* __restrict__ b1)
{
    extern __shared__ float dsm[];
    float* T1s  = dsm;                // 8192
    float* T2s  = dsm + 8192;         // 4096
    float* W1s  = dsm + 12288;        // 3136
    float* b1s  = dsm + 15424;        // 64
    float* mw2s = dsm + 15488;        // 64
    float* red  = dsm + 15552;        // 68

    const int n = blockIdx.x;
    const int tid = threadIdx.x;
    const int lane = tid & 31, wid = tid >> 5;

    uint32_t sb;
    { uint64_t t = __cvta_generic_to_shared(dsm); sb = (uint32_t)t; }

    // async-stage t1, t2 into smem
    {
        const float* t1 = g_tmp1 + (size_t)n * 8192;
#pragma unroll
        for (int p = 0; p < 4; p++) {
            const int i = tid + (p << 9);
            cp_async16(sb + (uint32_t)i * 16u, t1 + i * 4);
        }
        const float* t2 = g_tmp2 + (size_t)n * 4096;
#pragma unroll
        for (int p = 0; p < 2; p++) {
            const int i = tid + (p << 9);
            cp_async16(sb + 32768u + (uint32_t)i * 16u, t2 + i * 4);
        }
        cp_commit();
    }

    // while loads fly: stage weights
    for (int idx = tid; idx < 3136; idx += 512) {
        const int s = idx / 56, t = idx % 56;
        W1s[idx] = (t <= s) ? w1[idx] : 0.f;
    }
    if (tid < 56) b1s[tid] = b1[tid];
    if (tid < 57) mw2s[tid] = g_mw2[tid];

    cp_wait<0>();
    __syncthreads();

    // joint-LN stats from smem
    float s1 = 0.f, q1 = 0.f, s2 = 0.f, q2 = 0.f;
    for (int i = tid; i < 8192; i += 512) { const float v = T1s[i]; s1 += v; q1 += v * v; }
    for (int i = tid; i < 4096; i += 512) { const float v = T2s[i]; s2 += v; q2 += v * v; }
#pragma unroll
    for (int o = 16; o; o >>= 1) {
        s1 += __shfl_xor_sync(0xffffffffu, s1, o);
        q1 += __shfl_xor_sync(0xffffffffu, q1, o);
        s2 += __shfl_xor_sync(0xffffffffu, s2, o);
        q2 += __shfl_xor_sync(0xffffffffu, q2, o);
    }
    if (lane == 0) { red[wid] = s1; red[16 + wid] = q1; red[32 + wid] = s2; red[48 + wid] = q2; }
    __syncthreads();
    if (tid == 0) {
        float a = 0.f, b = 0.f, c = 0.f, d = 0.f;
        for (int i = 0; i < 16; i++) { a += red[i]; b += red[16 + i]; c += red[32 + i]; d += red[48 + i]; }
        const float m1 = a / 8192.f, v1 = b / 8192.f - m1 * m1;
        const float m2 = c / 4096.f, v2 = d / 4096.f - m2 * m2;
        red[64] = m1; red[65] = rsqrtf(v1 + 1e-5f);
        red[66] = m2; red[67] = rsqrtf(v2 + 1e-5f);
    }
    __syncthreads();
    const float m1 = red[64], rs1 = red[65], m2 = red[66], rs2 = red[67];

    // build v[56]: x read directly (coalesced across tid), t1/t2 from smem
    const int c = tid;
    float v[56];
    {
        const float* xp = x + (size_t)n * 16384 + c;
#pragma unroll
        for (int t = 0; t < 32; t++) v[t] = __ldg(xp + t * 512);
    }
#pragma unroll
    for (int t = 0; t < 16; t++) {
        const float r = T1s[t * 512 + c];
        v[32 + t] = (r - m1) * rs1 * ln1g[t * 512 + c] + ln1b[t * 512 + c];
    }
#pragma unroll
    for (int t = 0; t < 8; t++) {
        const float r = T2s[t * 512 + c];
        v[48 + t] = (r - m2) * rs2 * ln2g[t * 512 + c] + ln2b[t * 512 + c];
    }

    float acc = mw2s[56];
#pragma unroll
    for (int s = 0; s < 56; s++) {
        float u0 = b1s[s], u1 = 0.f, u2 = 0.f, u3 = 0.f;
        const int tmax = (s & ~3) + 4;
#pragma unroll
        for (int t = 0; t < 56; t += 4) {
            if (t < tmax) {
                const float4 w = *(const float4*)(W1s + s * 56 + t);
                u0 += v[t] * w.x;
                u1 += v[t + 1] * w.y;
                u2 += v[t + 2] * w.z;
                u3 += v[t + 3] * w.w;
            }
        }
        const float u = (u0 + u1) + (u2 + u3);
        const float hs = u * fminf(fmaxf(u + 3.f, 0.f), 6.f) * (1.f / 6.f);
        acc += hs * mw2s[s];
    }
    g_pooled[(size_t)n * 512 + c] = acc;
}

// ---------------- block-sparse attention: CTA = (industry, head) ----------------
__global__ void __launch_bounds__(128) attn_kernel() {
    extern __shared__ float sm[];
    const int g = blockIdx.x, h = blockIdx.y;
    const int tid = threadIdx.x;
    const int lane = tid & 31, warp = tid >> 5;
    const int off = g_offsets[g];
    int m = g_counts[g];
    if (m > GMAX) m = GMAX;
    if (m == 0) return;

    float* ks = sm;
    float* vs = ks + GMAX * 65;
    float* qsb = vs + GMAX * 65;
    float* psb = qsb + 4 * 64;
    float* qs = qsb + warp * 64;
    float* ps = psb + warp * GMAX;

    for (int idx = tid; idx < m * 64; idx += 128) {
        const int j = idx >> 6, d = idx & 63;
        const int nn = g_order[off + j];
        ks[j * 65 + d] = g_k[(size_t)nn * 512 + h * 64 + d];
        vs[j * 65 + d] = g_v[(size_t)nn * 512 + h * 64 + d];
    }
    __syncthreads();

    for (int qi = warp; qi < m; qi += 4) {
        const int nq = g_order[off + qi];
        qs[lane]      = g_q[(size_t)nq * 512 + h * 64 + lane];
        qs[lane + 32] = g_q[(size_t)nq * 512 + h * 64 + lane + 32];
        __syncwarp();
        float sc[4];
        float mx = -1e30f;
#pragma unroll
        for (int rep = 0; rep < 4; rep++) {
            const int j = lane + rep * 32;
            if (j < m) {
                float s = 0.f;
#pragma unroll
                for (int d = 0; d < 64; d++) s += qs[d] * ks[j * 65 + d];
                s *= 0.125f;
                sc[rep] = s;
                mx = fmaxf(mx, s);
            } else sc[rep] = -1e30f;
        }
#pragma unroll
        for (int o = 16; o; o >>= 1) mx = fmaxf(mx, __shfl_xor_sync(0xffffffffu, mx, o));
        float sum = 0.f;
#pragma unroll
        for (int rep = 0; rep < 4; rep++) {
            const int j = lane + rep * 32;
            if (j < m) {
                const float e = __expf(sc[rep] - mx);
                ps[j] = e;
                sum += e;
            }
        }
#pragma unroll
        for (int o = 16; o; o >>= 1) sum += __shfl_xor_sync(0xffffffffu, sum, o);
        const float inv = 1.f / sum;
        __syncwarp();
        float o0 = 0.f, o1 = 0.f;
        for (int j = 0; j < m; j++) {
            const float p = ps[j];
            o0 += p * vs[j * 65 + lane];
            o1 += p * vs[j * 65 + lane + 32];
        }
        g_attnout[(size_t)nq * 512 + h * 64 + lane]      = o0 * inv;
        g_attnout[(size_t)nq * 512 + h * 64 + lane + 32] = o1 * inv;
        __syncwarp();
    }
}

// ---------------- launcher ----------------
extern "C" void kernel_launch(void* const* d_in, const int* in_sizes, int n_in,
                              void* d_out, int out_size) {
    const float* x       = (const float*)d_in[0];
    const int*   ids     = (const int*)d_in[1];
    const float* conv1_w = (const float*)d_in[2];
    const float* conv1_b = (const float*)d_in[3];
    const float* conv2_w = (const float*)d_in[4];
    const float* conv2_b = (const float*)d_in[5];
    const float* ln1_g   = (const float*)d_in[6];
    const float* ln1_b   = (const float*)d_in[7];
    const float* ln2_g   = (const float*)d_in[8];
    const float* ln2_b   = (const float*)d_in[9];
    const float* triu_w1 = (const float*)d_in[10];
    const float* triu_b1 = (const float*)d_in[11];
    const float* triu_w2 = (const float*)d_in[12];
    const float* triu_b2 = (const float*)d_in[13];
    const float* wq = (const float*)d_in[14];
    const float* bq = (const float*)d_in[15];
    const float* wk = (const float*)d_in[16];
    const float* bk = (const float*)d_in[17];
    const float* wv = (const float*)d_in[18];
    const float* bv = (const float*)d_in[19];
    const float* wo = (const float*)d_in[20];
    const float* bo = (const float*)d_in[21];
    const float* wp = (const float*)d_in[22];
    const float* bp = (const float*)d_in[23];
    float* out = (float*)d_out;

    float *dT1, *dT2, *dPool, *dQ, *dK, *dV, *dAO;
    cudaGetSymbolAddress((void**)&dT1,  g_tmp1);
    cudaGetSymbolAddress((void**)&dT2,  g_tmp2);
    cudaGetSymbolAddress((void**)&dPool, g_pooled);
    cudaGetSymbolAddress((void**)&dQ, g_q);
    cudaGetSymbolAddress((void**)&dK, g_k);
    cudaGetSymbolAddress((void**)&dV, g_v);
    cudaGetSymbolAddress((void**)&dAO, g_attnout);

    const int ATT_SMEM = (2 * GMAX * 65 + 4 * 64 + 4 * GMAX) * 4;
    cudaFuncSetAttribute(attn_kernel, cudaFuncAttributeMaxDynamicSharedMemorySize, ATT_SMEM);
    cudaFuncSetAttribute(gemm_tc_conv_kernel, cudaFuncAttributeMaxDynamicSharedMemorySize, CV_SMEM);
    cudaFuncSetAttribute(gemm_tc_qkv_kernel, cudaFuncAttributeMaxDynamicSharedMemorySize, TC_SMEM);
    cudaFuncSetAttribute(gemm_tc_out_kernel, cudaFuncAttributeMaxDynamicSharedMemorySize, TC_SMEM);
    cudaFuncSetAttribute(triu_pool_kernel, cudaFuncAttributeMaxDynamicSharedMemorySize, TRIU_SMEM);

    // [1] merged weight prep (single launch)
    prep_all_kernel<<<7169, 256>>>(conv1_w, conv2_w, wq, wk, wv, wo, triu_w2, triu_b2);
    // [2] grouping
    group_kernel<<<1, 1024>>>(ids);
    // [3] conv1+conv2, M=256xN=256 3-stage
    gemm_tc_conv_kernel<<<384, 256, CV_SMEM>>>(x, conv1_b, conv2_b, dT1, dT2);
    // [4] fused LN + TriU1 + hardswish + folded TriU2/mean-pool (3 CTAs/SM; profiled slot)
    triu_pool_kernel<<<2048, 512, TRIU_SMEM>>>(x, ln1_g, ln1_b, ln2_g, ln2_b, triu_w1, triu_b1);
    // [5] fused QKV projections
    gemm_tc_qkv_kernel<<<dim3(16, 3), 256, TC_SMEM>>>(dPool, bq, bk, bv, dQ, dK, dV);
    // [6] block-sparse attention
    attn_kernel<<<dim3(64, 8), 128, ATT_SMEM>>>();
    // [7] out-proj + residual + final dot (fused)
    gemm_tc_out_kernel<<<16, 256, TC_SMEM>>>(dAO, bo, dPool, wp, bp, out);
}

// round 15
// speedup vs baseline: 1.0215x; 1.0215x over previous
#include <cuda_runtime.h>
#include <cstdint>
#include <cstddef>

#define NS   2048
#define CD   512
#define GMAX 128

#if defined(__CUDA_ARCH_FEAT_SM103_ALL) || defined(__CUDA_ARCH_FEAT_SM100_ALL) || defined(__CUDA_ARCH_FAMILY_SPECIFIC__)
#define HAS_TCGEN05 1
#else
#define HAS_TCGEN05 0
#endif

// ---------------- device scratch ----------------
__device__ float g_Wn1[512 * 1024];    // conv1 weight as [N=co][K=kk*512+ci]
__device__ float g_Wn2[512 * 2048];    // conv2 weight as [N=co][K]
__device__ float g_Wat[4 * 512 * 512]; // wq^T, wk^T, wv^T, wo^T as [N][K]
__device__ float g_tmp1[NS * 16 * CD];
__device__ float g_tmp2[NS * 8 * CD];
__device__ float g_pooled[NS * CD];
__device__ float g_q[NS * CD];
__device__ float g_k[NS * CD];
__device__ float g_v[NS * CD];
__device__ float g_attnout[NS * CD];
__device__ float g_mw2[64];
__device__ int   g_counts[64];
__device__ int   g_offsets[64];
__device__ int   g_order[NS];

// ---------------- common helpers ----------------
__device__ __forceinline__ uint32_t to_tf32_u(float x) {
    uint32_t u;
    asm("cvt.rna.tf32.f32 %0, %1;" : "=r"(u) : "f"(x));
    return u;
}
__device__ __forceinline__ void mma_tf32(float* d, const uint32_t* a, const uint32_t* b) {
    asm volatile(
        "mma.sync.aligned.m16n8k8.row.col.f32.tf32.tf32.f32 "
        "{%0,%1,%2,%3}, {%4,%5,%6,%7}, {%8,%9}, {%0,%1,%2,%3};\n"
        : "+f"(d[0]), "+f"(d[1]), "+f"(d[2]), "+f"(d[3])
        : "r"(a[0]), "r"(a[1]), "r"(a[2]), "r"(a[3]), "r"(b[0]), "r"(b[1]));
}
__device__ __forceinline__ void cp_async16(uint32_t dst, const void* src) {
    asm volatile("cp.async.cg.shared.global [%0], [%1], 16;\n" :: "r"(dst), "l"(src));
}
__device__ __forceinline__ void cp_commit() {
    asm volatile("cp.async.commit_group;\n");
}
template <int N>
__device__ __forceinline__ void cp_wait() {
    asm volatile("cp.async.wait_group %0;\n" :: "n"(N));
}
__device__ __forceinline__ uint32_t elect_one_pred() {
    uint32_t pred;
    asm volatile(
        "{\n\t.reg .pred p;\n\telect.sync _|p, 0xFFFFFFFF;\n\t"
        "selp.b32 %0, 1, 0, p;\n\t}" : "=r"(pred));
    return pred;
}
__device__ __forceinline__ uint32_t swz128(uint32_t off) {
    return off ^ ((off >> 3) & 0x70u);
}

#define MBARRIER_INIT(mbar_smem_addr, count) \
    asm volatile("mbarrier.init.shared.b64 [%0], %1;" \
        :: "r"((uint32_t)(mbar_smem_addr)), "r"((uint32_t)(count)) : "memory")
#define MBARRIER_WAIT_PARITY(mbar_smem_addr, phase_parity) do { \
    uint32_t _mbar = (uint32_t)(mbar_smem_addr); \
    uint32_t _parity = (uint32_t)(phase_parity); \
    uint32_t _done; \
    asm volatile( \
        "{\n\t.reg .pred p;\n\t" \
        "mbarrier.try_wait.parity.acquire.cta.shared::cta.b64 p, [%1], %2;\n\t" \
        "selp.b32 %0, 1, 0, p;\n\t}" \
        : "=r"(_done) : "r"(_mbar), "r"(_parity) : "memory"); \
    if (!_done) { \
        asm volatile( \
            "{\n\t.reg .pred P1;\n\t" \
            "WAIT_LOOP_%=:\n\t" \
            "mbarrier.try_wait.parity.acquire.cta.shared::cta.b64 P1, [%0], %1, 0x989680;\n\t" \
            "@P1 bra.uni WAIT_DONE_%=;\n\t" \
            "bra.uni WAIT_LOOP_%=;\n\t" \
            "WAIT_DONE_%=:\n\t}" \
            :: "r"(_mbar), "r"(_parity) : "memory"); \
    } \
} while(0)

#if HAS_TCGEN05
// ---------------- tcgen05 plumbing (arch-specific targets only) ----------------
#define TCGEN05_ALLOC(smem_addr, nCols) \
    asm volatile("tcgen05.alloc.cta_group::1.sync.aligned.shared::cta.b32 [%0], %1;" \
        :: "r"((uint32_t)(smem_addr)), "r"((uint32_t)(nCols)) : "memory")
#define TCGEN05_DEALLOC(tmem_addr, nCols) \
    asm volatile("tcgen05.dealloc.cta_group::1.sync.aligned.b32 %0, %1;" \
        :: "r"(tmem_addr), "r"((uint32_t)(nCols)))
#define TCGEN05_COMMIT(mbar_smem_addr) \
    asm volatile("tcgen05.commit.cta_group::1.mbarrier::arrive::one.shared::cluster.b64 [%0];" \
        :: "r"((uint32_t)(mbar_smem_addr)) : "memory")
#define TCGEN05_FENCE_AFTER() \
    asm volatile("tcgen05.fence::after_thread_sync;" ::: "memory")
#define TCGEN05_FENCE_BEFORE() \
    asm volatile("tcgen05.fence::before_thread_sync;" ::: "memory")
#define TCGEN05_WAIT_LD() \
    asm volatile("tcgen05.wait::ld.sync.aligned;" ::: "memory")
#define TCGEN05_LD_32X32B_X32(r, tmem_addr) \
    asm volatile( \
        "tcgen05.ld.sync.aligned.32x32b.x32.b32 " \
        "{%0, %1, %2, %3, %4, %5, %6, %7, " \
        " %8, %9, %10, %11, %12, %13, %14, %15, " \
        " %16, %17, %18, %19, %20, %21, %22, %23, " \
        " %24, %25, %26, %27, %28, %29, %30, %31}, [%32];" \
        : "=r"((r)[0]),  "=r"((r)[1]),  "=r"((r)[2]),  "=r"((r)[3]), \
          "=r"((r)[4]),  "=r"((r)[5]),  "=r"((r)[6]),  "=r"((r)[7]), \
          "=r"((r)[8]),  "=r"((r)[9]),  "=r"((r)[10]), "=r"((r)[11]), \
          "=r"((r)[12]), "=r"((r)[13]), "=r"((r)[14]), "=r"((r)[15]), \
          "=r"((r)[16]), "=r"((r)[17]), "=r"((r)[18]), "=r"((r)[19]), \
          "=r"((r)[20]), "=r"((r)[21]), "=r"((r)[22]), "=r"((r)[23]), \
          "=r"((r)[24]), "=r"((r)[25]), "=r"((r)[26]), "=r"((r)[27]), \
          "=r"((r)[28]), "=r"((r)[29]), "=r"((r)[30]), "=r"((r)[31]) \
        : "r"(tmem_addr))

static constexpr uint64_t SMEM_DESC_BASE_SW128 =
    (uint64_t(2)  << 61) | (uint64_t(1) << 46) | (uint64_t(64) << 32) | (uint64_t(1) << 16);
__device__ __forceinline__ uint64_t make_desc(uint32_t base_addr) {
    return SMEM_DESC_BASE_SW128 | ((uint64_t)(base_addr >> 4) & 0x3FFF);
}
#define IDESC_TF32_128 0x8200910u

__device__ __forceinline__ void mma_tc_tf32(uint32_t d, uint64_t ad, uint64_t bd,
                                            uint32_t idesc, bool acc) {
    uint32_t en = acc ? 1u : 0u;
    uint32_t z = 0u;
    asm volatile(
        "{\n\t.reg .pred p;\n\t"
        "setp.ne.u32 p, %5, 0;\n\t"
        "tcgen05.mma.cta_group::1.kind::tf32 [%0], %1, %2, %3, {%4,%4,%4,%4}, p;\n\t"
        "}"
        :: "r"(d), "l"(ad), "l"(bd), "r"(idesc), "r"(z), "r"(en) : "memory");
}
#endif  // HAS_TCGEN05

// ---------------- cg1 tcgen05 GEMM body (M=128, N=512, 2-stage) ----------------
#define TCS_CTRL  1024
#define TCS_STAGE (80 * 1024)
#define TC_SMEM   (TCS_CTRL + 2 * TCS_STAGE)

__device__ __forceinline__ void gemm_tc_body(
    const float* __restrict__ A, const float* __restrict__ B,
    const float* __restrict__ bias, const float* __restrict__ res,
    float* __restrict__ C,
    const float* __restrict__ wp, const float* __restrict__ bp, float* __restrict__ out,
    int K, int m0, float* smem)
{
#if HAS_TCGEN05
    uint32_t sb;
    { uint64_t t = __cvta_generic_to_shared(smem); sb = (uint32_t)t; }
    const int tid = threadIdx.x;
    const int lane = tid & 31, wid = tid >> 5;

    if (wid == 0) TCGEN05_ALLOC(sb + 0, 512);
    if (tid == 0) { MBARRIER_INIT(sb + 8, 1); MBARRIER_INIT(sb + 16, 1); }
    __syncthreads();
    uint32_t tmem;
    asm volatile("ld.shared.b32 %0, [%1];" : "=r"(tmem) : "r"(sb + 0));

    const int NSLAB = K >> 5;

    auto issue = [&](int s) {
        const uint32_t base = sb + TCS_CTRL + (uint32_t)(s & 1) * TCS_STAGE;
        const int kt = s << 5;
#pragma unroll
        for (int p = 0; p < 4; p++) {
            const int id = tid + (p << 8);
            const int r = id >> 3;
            const uint32_t c = (uint32_t)(id & 7) << 4;
            cp_async16(base + swz128(r * 128u + c),
                       A + (size_t)(m0 + r) * K + kt + (c >> 2));
        }
        const uint32_t bbase = base + 16384u;
#pragma unroll
        for (int p = 0; p < 16; p++) {
            const int id = tid + (p << 8);
            const int rn = id >> 3;
            const uint32_t c = (uint32_t)(id & 7) << 4;
            cp_async16(bbase + ((uint32_t)(rn >> 7) << 14) + swz128((uint32_t)(rn & 127) * 128u + c),
                       B + (size_t)rn * K + kt + (c >> 2));
        }
        cp_commit();
    };

    int ph[2] = {0, 0};
    issue(0);
    for (int s = 0; s < NSLAB; s++) {
        if (s + 1 < NSLAB) {
            if (s + 1 >= 2) {
                const int st2 = (s + 1) & 1;
                MBARRIER_WAIT_PARITY(sb + 8 + st2 * 8, ph[st2]);
                ph[st2] ^= 1;
            }
            issue(s + 1);
        }
        if (s + 1 < NSLAB) cp_wait<1>(); else cp_wait<0>();
        asm volatile("fence.proxy.async;" ::: "memory");
        __syncthreads();
        if (wid == 0 && elect_one_pred()) {
            const int st = s & 1;
            const uint32_t abase = sb + TCS_CTRL + (uint32_t)st * TCS_STAGE;
            const uint64_t adesc = make_desc(abase);
#pragma unroll
            for (int k = 0; k < 4; k++) {
#pragma unroll
                for (int c = 0; c < 4; c++) {
                    const uint64_t bdesc = make_desc(abase + 16384u + (uint32_t)c * 16384u) + k * 2;
                    mma_tc_tf32(tmem + c * 128, adesc + k * 2, bdesc,
                                IDESC_TF32_128, !(s == 0 && k == 0));
                }
            }
            TCGEN05_COMMIT(sb + 8 + st * 8);
        }
    }

    {
        const int st = (NSLAB - 1) & 1;
        MBARRIER_WAIT_PARITY(sb + 8 + st * 8, ph[st]);
    }
    TCGEN05_FENCE_AFTER();

    if (tid < 256) { smem[256 + tid] = bias[tid]; smem[256 + 256 + tid] = bias[256 + tid]; }
    if (wp && tid < 256) { smem[768 + tid] = wp[tid]; smem[768 + 256 + tid] = wp[256 + tid]; }
    __syncthreads();
    const float* bias_s = smem + 256;
    const float* wp_s   = smem + 768;

    {
        const int sub = wid & 3;
        const int half = wid >> 2;
        const int row = m0 + sub * 32 + lane;
        float* crow = C ? (C + (size_t)row * 512) : nullptr;
        const float* rrow = res ? (res + (size_t)row * 512) : nullptr;
        float partial = 0.f;
#pragma unroll
        for (int ch = 0; ch < 8; ch++) {
            const int col0 = half * 256 + ch * 32;
            uint32_t r[32];
            TCGEN05_LD_32X32B_X32(r, tmem + col0);
            TCGEN05_WAIT_LD();
#pragma unroll
            for (int j = 0; j < 32; j += 4) {
                float4 v;
                v.x = __uint_as_float(r[j])     + bias_s[col0 + j];
                v.y = __uint_as_float(r[j + 1]) + bias_s[col0 + j + 1];
                v.z = __uint_as_float(r[j + 2]) + bias_s[col0 + j + 2];
                v.w = __uint_as_float(r[j + 3]) + bias_s[col0 + j + 3];
                if (rrow) {
                    const float4 rv = *(const float4*)(rrow + col0 + j);
                    v.x += rv.x; v.y += rv.y; v.z += rv.z; v.w += rv.w;
                }
                if (crow) *(float4*)(crow + col0 + j) = v;
                if (wp) {
                    partial += v.x * wp_s[col0 + j]     + v.y * wp_s[col0 + j + 1]
                             + v.z * wp_s[col0 + j + 2] + v.w * wp_s[col0 + j + 3];
                }
            }
        }
        if (wp) {
            smem[1280 + wid * 32 + lane] = partial;
            __syncthreads();
            if (wid < 4)
                out[m0 + wid * 32 + lane] =
                    smem[1280 + wid * 32 + lane] + smem[1280 + (wid + 4) * 32 + lane] + bp[0];
        }
    }
    TCGEN05_FENCE_BEFORE();
    __syncthreads();
    if (wid == 0) TCGEN05_DEALLOC(tmem, 512);
#else
    // --------- fallback (generic PTX pass): mma.sync, both operands K-major ---------
    const int tid = threadIdx.x;
    const int lane = tid & 31, wid = tid >> 5;
    const int wm = wid >> 2, wn = wid & 3;
    float* As = smem;
    float* Bs = smem + 128 * 36;
    float* opart = smem + 2 * 128 * 36;

    if (wp) { for (int i = tid; i < 128; i += 256) opart[i] = 0.f; }
    __syncthreads();

    float pd[4][2];
#pragma unroll
    for (int i = 0; i < 4; i++) { pd[i][0] = 0.f; pd[i][1] = 0.f; }

    for (int nc = 0; nc < 4; nc++) {
        float acc[4][4][4];
#pragma unroll
        for (int i = 0; i < 4; i++)
#pragma unroll
            for (int j = 0; j < 4; j++)
#pragma unroll
                for (int r = 0; r < 4; r++) acc[i][j][r] = 0.f;
        for (int kt = 0; kt < K; kt += 32) {
            __syncthreads();
#pragma unroll
            for (int p = 0; p < 4; p++) {
                const int id = tid + (p << 8);
                const int r = id >> 3, c = (id & 7) << 2;
                const float4 va = *(const float4*)(A + (size_t)(m0 + r) * K + kt + c);
                float4 t;
                t.x = __uint_as_float(to_tf32_u(va.x)); t.y = __uint_as_float(to_tf32_u(va.y));
                t.z = __uint_as_float(to_tf32_u(va.z)); t.w = __uint_as_float(to_tf32_u(va.w));
                *(float4*)(As + r * 36 + c) = t;
                const float4 vb = *(const float4*)(B + (size_t)(nc * 128 + r) * K + kt + c);
                float4 u;
                u.x = __uint_as_float(to_tf32_u(vb.x)); u.y = __uint_as_float(to_tf32_u(vb.y));
                u.z = __uint_as_float(to_tf32_u(vb.z)); u.w = __uint_as_float(to_tf32_u(vb.w));
                *(float4*)(Bs + r * 36 + c) = u;
            }
            __syncthreads();
#pragma unroll
            for (int k8 = 0; k8 < 4; k8++) {
                uint32_t af[4][4], bf[4][2];
#pragma unroll
                for (int mf = 0; mf < 4; mf++) {
                    const int r = wm * 64 + mf * 16 + (lane >> 2);
                    const int c = k8 * 8 + (lane & 3);
                    af[mf][0] = __float_as_uint(As[r * 36 + c]);
                    af[mf][1] = __float_as_uint(As[(r + 8) * 36 + c]);
                    af[mf][2] = __float_as_uint(As[r * 36 + c + 4]);
                    af[mf][3] = __float_as_uint(As[(r + 8) * 36 + c + 4]);
                }
#pragma unroll
                for (int nf = 0; nf < 4; nf++) {
                    const int cb = wn * 32 + nf * 8 + (lane >> 2);
                    const int rb = k8 * 8 + (lane & 3);
                    bf[nf][0] = __float_as_uint(Bs[cb * 36 + rb]);
                    bf[nf][1] = __float_as_uint(Bs[cb * 36 + rb + 4]);
                }
#pragma unroll
                for (int mf = 0; mf < 4; mf++)
#pragma unroll
                    for (int nf = 0; nf < 4; nf++) mma_tf32(acc[mf][nf], af[mf], bf[nf]);
            }
        }
#pragma unroll
        for (int mf = 0; mf < 4; mf++) {
            const int r0 = m0 + wm * 64 + mf * 16 + (lane >> 2);
#pragma unroll
            for (int nf = 0; nf < 4; nf++) {
                const int c0 = nc * 128 + wn * 32 + nf * 8 + ((lane & 3) << 1);
                float v0 = acc[mf][nf][0] + bias[c0];
                float v1 = acc[mf][nf][1] + bias[c0 + 1];
                float v2 = acc[mf][nf][2] + bias[c0];
                float v3 = acc[mf][nf][3] + bias[c0 + 1];
                if (res) {
                    v0 += res[(size_t)r0 * 512 + c0];
                    v1 += res[(size_t)r0 * 512 + c0 + 1];
                    v2 += res[(size_t)(r0 + 8) * 512 + c0];
                    v3 += res[(size_t)(r0 + 8) * 512 + c0 + 1];
                }
                if (C) {
                    C[(size_t)r0 * 512 + c0]           = v0;
                    C[(size_t)r0 * 512 + c0 + 1]       = v1;
                    C[(size_t)(r0 + 8) * 512 + c0]     = v2;
                    C[(size_t)(r0 + 8) * 512 + c0 + 1] = v3;
                }
                if (wp) {
                    pd[mf][0] += v0 * wp[c0] + v1 * wp[c0 + 1];
                    pd[mf][1] += v2 * wp[c0] + v3 * wp[c0 + 1];
                }
            }
        }
    }
    if (wp) {
#pragma unroll
        for (int mf = 0; mf < 4; mf++) {
            const int r0 = wm * 64 + mf * 16 + (lane >> 2);
            atomicAdd(&opart[r0], pd[mf][0]);
            atomicAdd(&opart[r0 + 8], pd[mf][1]);
        }
        __syncthreads();
        for (int i = tid; i < 128; i += 256) out[m0 + i] = opart[i] + bp[0];
    }
#endif
}

// ---------------- conv GEMM: M=256 x N=256 tiles, 3-stage, lowest L2 traffic ----------------
#define CV_STAGE 65536
#define CV_SMEM  (1024 + 3 * CV_STAGE)   // 197632

__global__ void __launch_bounds__(256) gemm_tc_conv_kernel(
    const float* __restrict__ x,
    const float* __restrict__ conv1_b, const float* __restrict__ conv2_b,
    float* __restrict__ T1, float* __restrict__ T2)
{
    extern __shared__ float smem[];
    int K, m0, n0;
    const float* B; const float* bias_g; float* C;
    if (blockIdx.x < 128) {          // conv2: 64 supertiles x 2 N-halves
        K = 2048; C = T2; bias_g = conv2_b; B = g_Wn2;
        m0 = (blockIdx.x >> 1) << 8;
        n0 = (blockIdx.x & 1) << 8;
    } else {                          // conv1: 128 supertiles x 2 N-halves
        const int bi = blockIdx.x - 128;
        K = 1024; C = T1; bias_g = conv1_b; B = g_Wn1;
        m0 = (bi >> 1) << 8;
        n0 = (bi & 1) << 8;
    }
#if HAS_TCGEN05
    uint32_t sb;
    { uint64_t t = __cvta_generic_to_shared(smem); sb = (uint32_t)t; }
    const int tid = threadIdx.x;
    const int lane = tid & 31, wid = tid >> 5;

    if (wid == 0) TCGEN05_ALLOC(sb + 0, 512);
    if (tid == 0) {
#pragma unroll
        for (int st = 0; st < 3; st++) MBARRIER_INIT(sb + 8 + st * 8, 1);
    }
    __syncthreads();
    uint32_t tmem;
    asm volatile("ld.shared.b32 %0, [%1];" : "=r"(tmem) : "r"(sb + 0));

    const int NSLAB = K >> 5;

    auto issue = [&](int s) {
        const uint32_t base = sb + 1024u + (uint32_t)(s % 3) * CV_STAGE;
        const int kt = s << 5;
#pragma unroll
        for (int p = 0; p < 8; p++) {
            const int id = tid + (p << 8);
            const int r = id >> 3;
            const uint32_t c = (uint32_t)(id & 7) << 4;
            cp_async16(base + ((uint32_t)(r >> 7) << 14) + swz128((uint32_t)(r & 127) * 128u + c),
                       x + (size_t)(m0 + r) * K + kt + (c >> 2));
        }
        const uint32_t bbase = base + 32768u;
#pragma unroll
        for (int p = 0; p < 8; p++) {
            const int id = tid + (p << 8);
            const int rn = id >> 3;
            const uint32_t c = (uint32_t)(id & 7) << 4;
            cp_async16(bbase + ((uint32_t)(rn >> 7) << 14) + swz128((uint32_t)(rn & 127) * 128u + c),
                       B + (size_t)(n0 + rn) * K + kt + (c >> 2));
        }
        cp_commit();
    };

    int eph[3] = {0, 0, 0};
    issue(0); if (NSLAB > 1) issue(1);
    for (int s = 0; s < NSLAB; s++) {
        if (s + 2 < NSLAB) {
            const int st2 = (s + 2) % 3;
            if (s + 2 >= 3) {
                MBARRIER_WAIT_PARITY(sb + 8 + st2 * 8, eph[st2]);
                eph[st2] ^= 1;
            }
            issue(s + 2);
        }
        if (s + 2 < NSLAB) cp_wait<2>();
        else if (s + 1 < NSLAB) cp_wait<1>();
        else cp_wait<0>();
        asm volatile("fence.proxy.async;" ::: "memory");
        __syncthreads();
        if (wid == 0 && elect_one_pred()) {
            const int st = s % 3;
            const uint32_t base = sb + 1024u + (uint32_t)st * CV_STAGE;
#pragma unroll
            for (int k = 0; k < 4; k++) {
#pragma unroll
                for (int t = 0; t < 2; t++) {
                    const uint64_t adesc = make_desc(base + (uint32_t)t * 16384u) + k * 2;
#pragma unroll
                    for (int c = 0; c < 2; c++) {
                        const uint64_t bdesc = make_desc(base + 32768u + (uint32_t)c * 16384u) + k * 2;
                        mma_tc_tf32(tmem + t * 256 + c * 128, adesc, bdesc,
                                    IDESC_TF32_128, !(s == 0 && k == 0));
                    }
                }
            }
            TCGEN05_COMMIT(sb + 8 + st * 8);
        }
    }

    {
        const int st = (NSLAB - 1) % 3;
        MBARRIER_WAIT_PARITY(sb + 8 + st * 8, eph[st]);
    }
    TCGEN05_FENCE_AFTER();

    if (tid < 256) smem[256 + tid] = bias_g[n0 + tid];
    __syncthreads();
    const float* bias_s = smem + 256;

    {
        const int tile = wid >> 2;
        const int sub = wid & 3;
        const int row = m0 + tile * 128 + sub * 32 + lane;
        float* crow = C + (size_t)row * 512 + n0;
#pragma unroll
        for (int ch = 0; ch < 8; ch++) {
            const int col0 = ch * 32;
            uint32_t r[32];
            TCGEN05_LD_32X32B_X32(r, tmem + tile * 256 + col0);
            TCGEN05_WAIT_LD();
#pragma unroll
            for (int j = 0; j < 32; j += 4) {
                float4 v;
                v.x = __uint_as_float(r[j])     + bias_s[col0 + j];
                v.y = __uint_as_float(r[j + 1]) + bias_s[col0 + j + 1];
                v.z = __uint_as_float(r[j + 2]) + bias_s[col0 + j + 2];
                v.w = __uint_as_float(r[j + 3]) + bias_s[col0 + j + 3];
                *(float4*)(crow + col0 + j) = v;
            }
        }
    }
    TCGEN05_FENCE_BEFORE();
    __syncthreads();
    if (wid == 0) TCGEN05_DEALLOC(tmem, 512);
#else
    gemm_tc_body(x, B, bias_g, nullptr, C, nullptr, nullptr, nullptr, K, m0, smem);
    __syncthreads();
    gemm_tc_body(x, B, bias_g, nullptr, C, nullptr, nullptr, nullptr, K, m0 + 128, smem);
#endif
}

// fused QKV
__global__ void __launch_bounds__(256) gemm_tc_qkv_kernel(
    const float* __restrict__ A,
    const float* __restrict__ bq, const float* __restrict__ bk, const float* __restrict__ bv,
    float* __restrict__ Cq, float* __restrict__ Ck, float* __restrict__ Cv)
{
    extern __shared__ float smem[];
    const int z = blockIdx.y;
    const float* B    = g_Wat + ((size_t)z << 18);
    const float* bias = (z == 0) ? bq : (z == 1) ? bk : bv;
    float* C          = (z == 0) ? Cq : (z == 1) ? Ck : Cv;
    gemm_tc_body(A, B, bias, nullptr, C, nullptr, nullptr, nullptr, 512, blockIdx.x * 128, smem);
}

// out-proj + residual + fused final dot -> out
__global__ void __launch_bounds__(256) gemm_tc_out_kernel(
    const float* __restrict__ A, const float* __restrict__ bo,
    const float* __restrict__ res,
    const float* __restrict__ wp, const float* __restrict__ bp, float* __restrict__ out)
{
    extern __shared__ float smem[];
    const float* B = g_Wat + ((size_t)3 << 18);
    gemm_tc_body(A, B, bo, res, nullptr, wp, bp, out, 512, blockIdx.x * 128, smem);
}

// ---------------- merged weight prep (single launch) ----------------
__global__ void __launch_bounds__(256) prep_all_kernel(
    const float* __restrict__ c1w, const float* __restrict__ c2w,
    const float* __restrict__ wq, const float* __restrict__ wk,
    const float* __restrict__ wv, const float* __restrict__ wo,
    const float* __restrict__ w2, const float* __restrict__ b2)
{
    const int b = blockIdx.x;
    const int tid = threadIdx.x;
    if (b < 2048) {
        const int idx = b * 256 + tid;
        const int co = idx >> 10, k = idx & 1023;
        const int kk = k >> 9, ci = k & 511;
        g_Wn1[idx] = c1w[(size_t)co * 1024 + ci * 2 + kk];
    } else if (b < 6144) {
        const int idx = (b - 2048) * 256 + tid;
        const int co = idx >> 11, k = idx & 2047;
        const int kk = k >> 9, ci = k & 511;
        g_Wn2[idx] = c2w[(size_t)co * 2048 + ci * 4 + kk];
    } else if (b < 7168) {
        __shared__ float tile[32][33];
        const int wb = b - 6144;
        const int which = wb >> 8;
        const float* src = (which == 0) ? wq : (which == 1) ? wk : (which == 2) ? wv : wo;
        const int bx = wb & 15, by = (wb >> 4) & 15;
        const int tx = tid & 31, ty = tid >> 5;
#pragma unroll
        for (int i = 0; i < 32; i += 8)
            tile[ty + i][tx] = src[(by * 32 + ty + i) * 512 + bx * 32 + tx];
        __syncthreads();
        float* dst = g_Wat + ((size_t)which << 18);
#pragma unroll
        for (int i = 0; i < 32; i += 8)
            dst[(bx * 32 + ty + i) * 512 + by * 32 + tx] = tile[tx][ty + i];
    } else {
        if (tid < 56) {
            float s = 0.f;
            for (int ss = tid; ss < 56; ss++) s += w2[ss * 56 + tid];
            g_mw2[tid] = s * (1.f / 56.f);
        } else if (tid == 56) {
            float s = 0.f;
            for (int i = 0; i < 56; i++) s += b2[i];
            g_mw2[56] = s * (1.f / 56.f);
        }
    }
}

// ---------------- parallel deterministic industry grouping ----------------
__global__ void __launch_bounds__(1024) group_kernel(const int* __restrict__ ids) {
    __shared__ int sid[NS];
    __shared__ int scnt[64], soff[64];
    const int tid = threadIdx.x;
    const int warp = tid >> 5, lane = tid & 31;
    sid[tid] = ids[tid];
    sid[tid + 1024] = ids[tid + 1024];
    __syncthreads();
#pragma unroll
    for (int g = warp; g < 64; g += 32) {
        int cnt = 0;
        for (int c = 0; c < NS; c += 32)
            cnt += __popc(__ballot_sync(0xffffffffu, sid[c + lane] == g));
        if (lane == 0) scnt[g] = cnt;
    }
    __syncthreads();
    if (tid == 0) {
        int off = 0;
        for (int g = 0; g < 64; g++) {
            soff[g] = off; g_offsets[g] = off; g_counts[g] = scnt[g];
            off += scnt[g];
        }
    }
    __syncthreads();
#pragma unroll
    for (int g = warp; g < 64; g += 32) {
        int w = soff[g];
        for (int c = 0; c < NS; c += 32) {
            const bool hit = (sid[c + lane] == g);
            const unsigned m = __ballot_sync(0xffffffffu, hit);
            if (hit) g_order[w + __popc(m & ((1u << lane) - 1u))] = c + lane;
            w += __popc(m);
        }
    }
}

// ---------------- fused LN-stats + TriU1 + hardswish + folded(TriU2+mean) ----------------
// 256 threads, 2 channels/thread: each LDS.128 of a W row feeds 8 FMAs (halves LDS stream).
// smem: T1s 8192 | T2s 4096 | W1s 3136 | b1s 64 | mw2s 64 | red 68
#define TRIU_SMEM (15680 * 4)

__global__ void __launch_bounds__(256) triu_pool_kernel(
    const float* __restrict__ x,
    const float* __restrict__ ln1g, const float* __restrict__ ln1b,
    const float* __restrict__ ln2g, const float* __restrict__ ln2b,
    const float* __restrict__ w1, const float* __restrict__ b1)
{
    extern __shared__ float dsm[];
    float* T1s  = dsm;                // 8192
    float* T2s  = dsm + 8192;         // 4096
    float* W1s  = dsm + 12288;        // 3136
    float* b1s  = dsm + 15424;        // 64
    float* mw2s = dsm + 15488;        // 64
    float* red  = dsm + 15552;        // 68

    const int n = blockIdx.x;
    const int tid = threadIdx.x;
    const int lane = tid & 31, wid = tid >> 5;

    uint32_t sb;
    { uint64_t t = __cvta_generic_to_shared(dsm); sb = (uint32_t)t; }

    // async-stage t1, t2 into smem
    {
        const float* t1 = g_tmp1 + (size_t)n * 8192;
#pragma unroll
        for (int p = 0; p < 8; p++) {
            const int i = tid + (p << 8);
            cp_async16(sb + (uint32_t)i * 16u, t1 + i * 4);
        }
        const float* t2 = g_tmp2 + (size_t)n * 4096;
#pragma unroll
        for (int p = 0; p < 4; p++) {
            const int i = tid + (p << 8);
            cp_async16(sb + 32768u + (uint32_t)i * 16u, t2 + i * 4);
        }
        cp_commit();
    }

    // while loads fly: stage weights
    for (int idx = tid; idx < 3136; idx += 256) {
        const int s = idx / 56, t = idx % 56;
        W1s[idx] = (t <= s) ? w1[idx] : 0.f;
    }
    if (tid < 56) b1s[tid] = b1[tid];
    if (tid < 57) mw2s[tid] = g_mw2[tid];

    cp_wait<0>();
    __syncthreads();

    // joint-LN stats from smem (8 warps)
    float s1 = 0.f, q1 = 0.f, s2 = 0.f, q2 = 0.f;
    for (int i = tid; i < 8192; i += 256) { const float v = T1s[i]; s1 += v; q1 += v * v; }
    for (int i = tid; i < 4096; i += 256) { const float v = T2s[i]; s2 += v; q2 += v * v; }
#pragma unroll
    for (int o = 16; o; o >>= 1) {
        s1 += __shfl_xor_sync(0xffffffffu, s1, o);
        q1 += __shfl_xor_sync(0xffffffffu, q1, o);
        s2 += __shfl_xor_sync(0xffffffffu, s2, o);
        q2 += __shfl_xor_sync(0xffffffffu, q2, o);
    }
    if (lane == 0) { red[wid] = s1; red[8 + wid] = q1; red[16 + wid] = s2; red[24 + wid] = q2; }
    __syncthreads();
    if (tid == 0) {
        float a = 0.f, b = 0.f, c = 0.f, d = 0.f;
        for (int i = 0; i < 8; i++) { a += red[i]; b += red[8 + i]; c += red[16 + i]; d += red[24 + i]; }
        const float m1 = a / 8192.f, v1 = b / 8192.f - m1 * m1;
        const float m2 = c / 4096.f, v2 = d / 4096.f - m2 * m2;
        red[64] = m1; red[65] = rsqrtf(v1 + 1e-5f);
        red[66] = m2; red[67] = rsqrtf(v2 + 1e-5f);
    }
    __syncthreads();
    const float m1 = red[64], rs1 = red[65], m2 = red[66], rs2 = red[67];

    // build v for channels c0 = tid and c1 = tid + 256
    const int c0i = tid, c1i = tid + 256;
    float va[56], vb[56];
    {
        const float* xp = x + (size_t)n * 16384;
#pragma unroll
        for (int t = 0; t < 32; t++) {
            va[t] = __ldg(xp + t * 512 + c0i);
            vb[t] = __ldg(xp + t * 512 + c1i);
        }
    }
#pragma unroll
    for (int t = 0; t < 16; t++) {
        const float ra = T1s[t * 512 + c0i];
        const float rb = T1s[t * 512 + c1i];
        va[32 + t] = (ra - m1) * rs1 * ln1g[t * 512 + c0i] + ln1b[t * 512 + c0i];
        vb[32 + t] = (rb - m1) * rs1 * ln1g[t * 512 + c1i] + ln1b[t * 512 + c1i];
    }
#pragma unroll
    for (int t = 0; t < 8; t++) {
        const float ra = T2s[t * 512 + c0i];
        const float rb = T2s[t * 512 + c1i];
        va[48 + t] = (ra - m2) * rs2 * ln2g[t * 512 + c0i] + ln2b[t * 512 + c0i];
        vb[48 + t] = (rb - m2) * rs2 * ln2g[t * 512 + c1i] + ln2b[t * 512 + c1i];
    }

    float acca = mw2s[56], accb = acca;
#pragma unroll
    for (int s = 0; s < 56; s++) {
        const float bb = b1s[s];
        float a0 = bb, a1 = 0.f, a2 = 0.f, a3 = 0.f;
        float b0 = bb, b1v = 0.f, b2v = 0.f, b3 = 0.f;
        const int tmax = (s & ~3) + 4;  // zero-padded upper triangle
#pragma unroll
        for (int t = 0; t < 56; t += 4) {
            if (t < tmax) {
                const float4 w = *(const float4*)(W1s + s * 56 + t);
                a0 += va[t] * w.x;   b0  += vb[t] * w.x;
                a1 += va[t+1] * w.y; b1v += vb[t+1] * w.y;
                a2 += va[t+2] * w.z; b2v += vb[t+2] * w.z;
                a3 += va[t+3] * w.w; b3  += vb[t+3] * w.w;
            }
        }
        const float ua = (a0 + a1) + (a2 + a3);
        const float ub = (b0 + b1v) + (b2v + b3);
        const float mw = mw2s[s];
        acca += (ua * fminf(fmaxf(ua + 3.f, 0.f), 6.f) * (1.f / 6.f)) * mw;
        accb += (ub * fminf(fmaxf(ub + 3.f, 0.f), 6.f) * (1.f / 6.f)) * mw;
    }
    g_pooled[(size_t)n * 512 + c0i] = acca;
    g_pooled[(size_t)n * 512 + c1i] = accb;
}

// ---------------- block-sparse attention: CTA = (industry, head) ----------------
__global__ void __launch_bounds__(128) attn_kernel() {
    extern __shared__ float sm[];
    const int g = blockIdx.x, h = blockIdx.y;
    const int tid = threadIdx.x;
    const int lane = tid & 31, warp = tid >> 5;
    const int off = g_offsets[g];
    int m = g_counts[g];
    if (m > GMAX) m = GMAX;
    if (m == 0) return;

    float* ks = sm;
    float* vs = ks + GMAX * 65;
    float* qsb = vs + GMAX * 65;
    float* psb = qsb + 4 * 64;
    float* qs = qsb + warp * 64;
    float* ps = psb + warp * GMAX;

    for (int idx = tid; idx < m * 64; idx += 128) {
        const int j = idx >> 6, d = idx & 63;
        const int nn = g_order[off + j];
        ks[j * 65 + d] = g_k[(size_t)nn * 512 + h * 64 + d];
        vs[j * 65 + d] = g_v[(size_t)nn * 512 + h * 64 + d];
    }
    __syncthreads();

    for (int qi = warp; qi < m; qi += 4) {
        const int nq = g_order[off + qi];
        qs[lane]      = g_q[(size_t)nq * 512 + h * 64 + lane];
        qs[lane + 32] = g_q[(size_t)nq * 512 + h * 64 + lane + 32];
        __syncwarp();
        float sc[4];
        float mx = -1e30f;
#pragma unroll
        for (int rep = 0; rep < 4; rep++) {
            const int j = lane + rep * 32;
            if (j < m) {
                float s = 0.f;
#pragma unroll
                for (int d = 0; d < 64; d++) s += qs[d] * ks[j * 65 + d];
                s *= 0.125f;
                sc[rep] = s;
                mx = fmaxf(mx, s);
            } else sc[rep] = -1e30f;
        }
#pragma unroll
        for (int o = 16; o; o >>= 1) mx = fmaxf(mx, __shfl_xor_sync(0xffffffffu, mx, o));
        float sum = 0.f;
#pragma unroll
        for (int rep = 0; rep < 4; rep++) {
            const int j = lane + rep * 32;
            if (j < m) {
                const float e = __expf(sc[rep] - mx);
                ps[j] = e;
                sum += e;
            }
        }
#pragma unroll
        for (int o = 16; o; o >>= 1) sum += __shfl_xor_sync(0xffffffffu, sum, o);
        const float inv = 1.f / sum;
        __syncwarp();
        float o0 = 0.f, o1 = 0.f;
        for (int j = 0; j < m; j++) {
            const float p = ps[j];
            o0 += p * vs[j * 65 + lane];
            o1 += p * vs[j * 65 + lane + 32];
        }
        g_attnout[(size_t)nq * 512 + h * 64 + lane]      = o0 * inv;
        g_attnout[(size_t)nq * 512 + h * 64 + lane + 32] = o1 * inv;
        __syncwarp();
    }
}

// ---------------- launcher ----------------
extern "C" void kernel_launch(void* const* d_in, const int* in_sizes, int n_in,
                              void* d_out, int out_size) {
    const float* x       = (const float*)d_in[0];
    const int*   ids     = (const int*)d_in[1];
    const float* conv1_w = (const float*)d_in[2];
    const float* conv1_b = (const float*)d_in[3];
    const float* conv2_w = (const float*)d_in[4];
    const float* conv2_b = (const float*)d_in[5];
    const float* ln1_g   = (const float*)d_in[6];
    const float* ln1_b   = (const float*)d_in[7];
    const float* ln2_g   = (const float*)d_in[8];
    const float* ln2_b   = (const float*)d_in[9];
    const float* triu_w1 = (const float*)d_in[10];
    const float* triu_b1 = (const float*)d_in[11];
    const float* triu_w2 = (const float*)d_in[12];
    const float* triu_b2 = (const float*)d_in[13];
    const float* wq = (const float*)d_in[14];
    const float* bq = (const float*)d_in[15];
    const float* wk = (const float*)d_in[16];
    const float* bk = (const float*)d_in[17];
    const float* wv = (const float*)d_in[18];
    const float* bv = (const float*)d_in[19];
    const float* wo = (const float*)d_in[20];
    const float* bo = (const float*)d_in[21];
    const float* wp = (const float*)d_in[22];
    const float* bp = (const float*)d_in[23];
    float* out = (float*)d_out;

    float *dT1, *dT2, *dPool, *dQ, *dK, *dV, *dAO;
    cudaGetSymbolAddress((void**)&dT1,  g_tmp1);
    cudaGetSymbolAddress((void**)&dT2,  g_tmp2);
    cudaGetSymbolAddress((void**)&dPool, g_pooled);
    cudaGetSymbolAddress((void**)&dQ, g_q);
    cudaGetSymbolAddress((void**)&dK, g_k);
    cudaGetSymbolAddress((void**)&dV, g_v);
    cudaGetSymbolAddress((void**)&dAO, g_attnout);

    const int ATT_SMEM = (2 * GMAX * 65 + 4 * 64 + 4 * GMAX) * 4;
    cudaFuncSetAttribute(attn_kernel, cudaFuncAttributeMaxDynamicSharedMemorySize, ATT_SMEM);
    cudaFuncSetAttribute(gemm_tc_conv_kernel, cudaFuncAttributeMaxDynamicSharedMemorySize, CV_SMEM);
    cudaFuncSetAttribute(gemm_tc_qkv_kernel, cudaFuncAttributeMaxDynamicSharedMemorySize, TC_SMEM);
    cudaFuncSetAttribute(gemm_tc_out_kernel, cudaFuncAttributeMaxDynamicSharedMemorySize, TC_SMEM);
    cudaFuncSetAttribute(triu_pool_kernel, cudaFuncAttributeMaxDynamicSharedMemorySize, TRIU_SMEM);

    // [1] merged weight prep (single launch)
    prep_all_kernel<<<7169, 256>>>(conv1_w, conv2_w, wq, wk, wv, wo, triu_w2, triu_b2);
    // [2] grouping
    group_kernel<<<1, 1024>>>(ids);
    // [3] conv1+conv2, M=256xN=256 3-stage
    gemm_tc_conv_kernel<<<384, 256, CV_SMEM>>>(x, conv1_b, conv2_b, dT1, dT2);
    // [4] fused LN + TriU1 + hardswish + folded TriU2/mean-pool (2ch/thread; profiled slot)
    triu_pool_kernel<<<2048, 256, TRIU_SMEM>>>(x, ln1_g, ln1_b, ln2_g, ln2_b, triu_w1, triu_b1);
    // [5] fused QKV projections
    gemm_tc_qkv_kernel<<<dim3(16, 3), 256, TC_SMEM>>>(dPool, bq, bk, bv, dQ, dK, dV);
    // [6] block-sparse attention
    attn_kernel<<<dim3(64, 8), 128, ATT_SMEM>>>();
    // [7] out-proj + residual + final dot (fused)
    gemm_tc_out_kernel<<<16, 256, TC_SMEM>>>(dAO, bo, dPool, wp, bp, out);
}